// round 1
// baseline (speedup 1.0000x reference)
#include <cuda_runtime.h>
#include <math.h>

#define BATCH 64
#define CH    64
#define NPT   256
#define NQK   8
#define NVC   32
#define NSTK  16

// ---------------- global scratch (no allocations allowed) ----------------
__device__ float g_q_ga[BATCH * NPT * NQK];
__device__ float g_k_ga[BATCH * NPT * NQK];
__device__ float g_v_ga[BATCH * NPT * NVC];
__device__ float g_q_sa[BATCH * NPT * NQK];
__device__ float g_k_sa[BATCH * NPT * NQK];
__device__ float g_v_sa[BATCH * NPT * NVC];
__device__ float g_lb_ga[BATCH * NVC * NPT];
__device__ float g_lb_sa[BATCH * NVC * NPT];
__device__ float g_f[BATCH * CH * NPT];

// ---------------- helpers ----------------
__device__ __forceinline__ float dot8f(const float4 q0, const float4 q1,
                                       const float4 k0, const float4 k1) {
    float d = q0.x * k0.x;
    d = fmaf(q0.y, k0.y, d);
    d = fmaf(q0.z, k0.z, d);
    d = fmaf(q0.w, k0.w, d);
    d = fmaf(q1.x, k1.x, d);
    d = fmaf(q1.y, k1.y, d);
    d = fmaf(q1.z, k1.z, d);
    d = fmaf(q1.w, k1.w, d);
    return d;
}

__device__ __forceinline__ void bn_coef(const float* __restrict__ p, int ch, int cn,
                                        float& sc, float& sh) {
    float ga = __ldg(p + ch);
    float be = __ldg(p + cn + ch);
    float mu = __ldg(p + 2 * cn + ch);
    float va = __ldg(p + 3 * cn + ch);
    sc = ga * rsqrtf(va + 1e-5f);
    sh = fmaf(-mu, sc, be);
}

__device__ __forceinline__ float dotrow64(const float* __restrict__ wrow,
                                          const float xr[64]) {
    float acc = 0.f;
    const float4* w4 = (const float4*)wrow;
#pragma unroll
    for (int i = 0; i < 16; i++) {
        float4 w = w4[i];
        acc = fmaf(w.x, xr[4 * i + 0], acc);
        acc = fmaf(w.y, xr[4 * i + 1], acc);
        acc = fmaf(w.z, xr[4 * i + 2], acc);
        acc = fmaf(w.w, xr[4 * i + 3], acc);
    }
    return acc;
}

// ---------------- kernel 1: all projections ----------------
// grid (64, 2), block 128. Thread = one point column n. x column in registers.
__global__ void proj_kernel(const float* __restrict__ x,
                            const float* __restrict__ ga_q_w, const float* __restrict__ ga_k_w,
                            const float* __restrict__ ga_v_w, const float* __restrict__ ga_v_b,
                            const float* __restrict__ ga_lb_w,
                            const float* __restrict__ sa_q_w, const float* __restrict__ sa_k_w,
                            const float* __restrict__ sa_v_w, const float* __restrict__ sa_v_b,
                            const float* __restrict__ sa_lb_w) {
    __shared__ float ws[160 * 64];
    int b = blockIdx.x, tid = threadIdx.x;
    int n = blockIdx.y * 128 + tid;

    for (int i = tid; i < 512;  i += 128) ws[i]        = ga_q_w[i];
    for (int i = tid; i < 512;  i += 128) ws[512 + i]  = ga_k_w[i];
    for (int i = tid; i < 2048; i += 128) ws[1024 + i] = ga_v_w[i];
    for (int i = tid; i < 512;  i += 128) ws[3072 + i] = sa_q_w[i];
    for (int i = tid; i < 512;  i += 128) ws[3584 + i] = sa_k_w[i];
    for (int i = tid; i < 2048; i += 128) ws[4096 + i] = sa_v_w[i];
    for (int i = tid; i < 2048; i += 128) ws[6144 + i] = ga_lb_w[i];
    for (int i = tid; i < 2048; i += 128) ws[8192 + i] = sa_lb_w[i];
    __syncthreads();

    float xr[64];
#pragma unroll
    for (int c = 0; c < 64; c++) xr[c] = __ldg(&x[b * 16384 + c * 256 + n]);

    int rn = b * 256 + n;
#pragma unroll 2
    for (int o = 0; o < 8; o++)  g_q_ga[rn * 8 + o] = dotrow64(ws + o * 64, xr);
#pragma unroll 2
    for (int o = 0; o < 8; o++)  g_k_ga[rn * 8 + o] = dotrow64(ws + (8 + o) * 64, xr);
#pragma unroll 2
    for (int o = 0; o < 32; o++) g_v_ga[rn * 32 + o] = dotrow64(ws + (16 + o) * 64, xr) + __ldg(ga_v_b + o);
#pragma unroll 2
    for (int o = 0; o < 8; o++)  g_q_sa[rn * 8 + o] = dotrow64(ws + (48 + o) * 64, xr);
#pragma unroll 2
    for (int o = 0; o < 8; o++)  g_k_sa[rn * 8 + o] = dotrow64(ws + (56 + o) * 64, xr);
#pragma unroll 2
    for (int o = 0; o < 32; o++) g_v_sa[rn * 32 + o] = dotrow64(ws + (64 + o) * 64, xr) + __ldg(sa_v_b + o);
#pragma unroll 2
    for (int v = 0; v < 32; v++) g_lb_ga[b * 8192 + v * 256 + n] = dotrow64(ws + (96 + v) * 64, xr);
#pragma unroll 2
    for (int v = 0; v < 32; v++) g_lb_sa[b * 8192 + v * 256 + n] = dotrow64(ws + (128 + v) * 64, xr);
}

// ---------------- kernel 2: dual attention + BN + lb fusion -> f ----------------
// grid (64, 2), block 128. Thread = one query row n. ~91 KB dyn smem.
#define SMEM_A_BYTES ((2048 + 2048 + 8192 + 8192 + 2048 + 256) * 4)

__global__ void attn_kernel(const int* __restrict__ stroke_idx,
                            const float* __restrict__ ga_bn_p, const float* __restrict__ ga_lb_bn_p,
                            const float* __restrict__ sa_bn_p, const float* __restrict__ sa_lb_bn_p) {
    extern __shared__ float sm[];
    float* Kga = sm;                 // 256*8
    float* Ksa = sm + 2048;          // 256*8
    float* Vga = sm + 4096;          // 256*32
    float* Vsa = sm + 12288;         // 256*32
    float* EsS = sm + 20480;         // 16*128 (per-thread stroke bins)
    int*   stk = (int*)(sm + 22528); // 256

    int b = blockIdx.x, tid = threadIdx.x;
    for (int i = tid; i < 2048; i += 128) { Kga[i] = g_k_ga[b * 2048 + i]; Ksa[i] = g_k_sa[b * 2048 + i]; }
    for (int i = tid; i < 8192; i += 128) { Vga[i] = g_v_ga[b * 8192 + i]; Vsa[i] = g_v_sa[b * 8192 + i]; }
    for (int i = tid; i < 256;  i += 128) stk[i] = stroke_idx[b * 256 + i];
    __syncthreads();

    int n  = blockIdx.y * 128 + tid;
    int rn = b * 256 + n;
    float4 qa0 = *(const float4*)&g_q_ga[rn * 8];
    float4 qa1 = *(const float4*)&g_q_ga[rn * 8 + 4];
    float4 qs0 = *(const float4*)&g_q_sa[rn * 8];
    float4 qs1 = *(const float4*)&g_q_sa[rn * 8 + 4];
    const float4* K4a = (const float4*)Kga;
    const float4* K4s = (const float4*)Ksa;
    const float4* V4a = (const float4*)Vga;
    const float4* V4s = (const float4*)Vsa;

    const float INV_GA = 0.35355339059327373f;   // 1/sqrt(8)
    const float ESC    = 3.5355339059327378f;    // 10/sqrt(8)

    // ---- pass 1: row maxima for both branches ----
    float mga = -1e30f, msa = -1e30f;
#pragma unroll 4
    for (int m = 0; m < 256; m++) {
        float d  = dot8f(qa0, qa1, K4a[2 * m], K4a[2 * m + 1]);
        float ds = dot8f(qs0, qs1, K4s[2 * m], K4s[2 * m + 1]);
        mga = fmaxf(mga, d);
        msa = fmaxf(msa, ds);
    }

    float oacc[32];

    // ---- GA: softmax + attn @ V ----
#pragma unroll
    for (int v = 0; v < 32; v++) oacc[v] = 0.f;
    float sum = 0.f;
#pragma unroll 2
    for (int m = 0; m < 256; m++) {
        float d = dot8f(qa0, qa1, K4a[2 * m], K4a[2 * m + 1]);
        float e = __expf((d - mga) * INV_GA);
        sum += e;
#pragma unroll
        for (int g = 0; g < 8; g++) {
            float4 vv = V4a[(m << 3) + g];
            oacc[g * 4 + 0] = fmaf(e, vv.x, oacc[g * 4 + 0]);
            oacc[g * 4 + 1] = fmaf(e, vv.y, oacc[g * 4 + 1]);
            oacc[g * 4 + 2] = fmaf(e, vv.z, oacc[g * 4 + 2]);
            oacc[g * 4 + 3] = fmaf(e, vv.w, oacc[g * 4 + 3]);
        }
    }
    float rcp = 1.f / sum;
#pragma unroll
    for (int v = 0; v < 32; v++) {
        float sc1, sh1, sc2, sh2;
        bn_coef(ga_bn_p, v, 32, sc1, sh1);
        bn_coef(ga_lb_bn_p, v, 32, sc2, sh2);
        float lb  = __ldg(&g_lb_ga[b * 8192 + v * 256 + n]);
        float val = fmaf(oacc[v] * rcp, sc1, sh1) + fmaf(lb, sc2, sh2);
        g_f[b * 16384 + v * 256 + n] = val;
    }

    // ---- SA: collapsed 16-stroke masked softmax sum ----
    // energy = 10*(qk/sqrt8) + 1e-5 on non-matching columns.
    // c = exp(1e-5); Z_s = c*E - (c-1)*E_s; weight(m, t=stk[m]) = e_m*(c*Sinv - (c-1)/Z_t)
    const float CC  = 1.00001000005f;
    const float CM1 = 1.00000500002e-05f;

#pragma unroll
    for (int s = 0; s < 16; s++) EsS[s * 128 + tid] = 0.f;
    float E = 0.f;
#pragma unroll 2
    for (int m = 0; m < 256; m++) {
        float ds = dot8f(qs0, qs1, K4s[2 * m], K4s[2 * m + 1]);
        float e  = __expf((ds - msa) * ESC);
        E += e;
        EsS[stk[m] * 128 + tid] += e;   // m uniform across warp -> conflict-free lane access
    }
    float Sinv = 0.f;
#pragma unroll
    for (int s = 0; s < 16; s++) {
        float z  = fmaf(-CM1, EsS[s * 128 + tid], CC * E);
        float zi = 1.f / z;
        EsS[s * 128 + tid] = zi;
        Sinv += zi;
    }
#pragma unroll
    for (int s = 0; s < 16; s++) {
        EsS[s * 128 + tid] = fmaf(-CM1, EsS[s * 128 + tid], CC * Sinv);  // coef_s
    }

#pragma unroll
    for (int v = 0; v < 32; v++) oacc[v] = 0.f;
#pragma unroll 2
    for (int m = 0; m < 256; m++) {
        float ds = dot8f(qs0, qs1, K4s[2 * m], K4s[2 * m + 1]);
        float e  = __expf((ds - msa) * ESC);
        float w  = e * EsS[stk[m] * 128 + tid];
#pragma unroll
        for (int g = 0; g < 8; g++) {
            float4 vv = V4s[(m << 3) + g];
            oacc[g * 4 + 0] = fmaf(w, vv.x, oacc[g * 4 + 0]);
            oacc[g * 4 + 1] = fmaf(w, vv.y, oacc[g * 4 + 1]);
            oacc[g * 4 + 2] = fmaf(w, vv.z, oacc[g * 4 + 2]);
            oacc[g * 4 + 3] = fmaf(w, vv.w, oacc[g * 4 + 3]);
        }
    }
#pragma unroll
    for (int v = 0; v < 32; v++) {
        float sc1, sh1, sc2, sh2;
        bn_coef(sa_bn_p, v, 32, sc1, sh1);
        bn_coef(sa_lb_bn_p, v, 32, sc2, sh2);
        float lb  = __ldg(&g_lb_sa[b * 8192 + v * 256 + n]);
        float val = fmaf(oacc[v], sc1, sh1) + fmaf(lb, sc2, sh2);
        g_f[b * 16384 + (32 + v) * 256 + n] = val;
    }
}

// ---------------- kernel 3: MLP (both conv1x1 + BN + relu + residual) ----------------
// grid (4, 64), block 256. ~219 KB dyn smem.
#define FS_OFF   0
#define W1T_OFF  4352                   // fs = 64*68
#define W2T_OFF  (4352 + 16448)         // w1t = 64*257
#define HS_OFF   (4352 + 16448 + 16640) // w2t = 256*65
#define SMEM_M_BYTES ((4352 + 16448 + 16640 + 17408) * 4)

__global__ void mlp_kernel(const float* __restrict__ w1, const float* __restrict__ bn1,
                           const float* __restrict__ w2, const float* __restrict__ bn2,
                           float* __restrict__ out) {
    extern __shared__ float sm[];
    float* fs  = sm + FS_OFF;
    float* w1t = sm + W1T_OFF;
    float* w2t = sm + W2T_OFF;
    float* hs  = sm + HS_OFF;

    int b = blockIdx.y, n0 = blockIdx.x * 64, tid = threadIdx.x;

    for (int i = tid; i < 4096; i += 256) {
        int c = i >> 6, nn = i & 63;
        fs[c * 68 + nn] = g_f[b * 16384 + c * 256 + n0 + nn];
    }
    for (int i = tid; i < 16384; i += 256) {        // w1 [256,64] -> w1t[c][o], stride 257
        int o = i >> 6, c = i & 63;
        w1t[c * 257 + o] = __ldg(&w1[i]);
    }
    for (int i = tid; i < 16384; i += 256) {        // w2 [64,256] -> w2t[o][c], stride 65
        int c = i >> 8, o = i & 255;
        w2t[o * 65 + c] = __ldg(&w2[i]);
    }
    __syncthreads();

    // stage 1: h[o][nn] = relu(bn1(sum_c w1[o][c] f[c][nn])), thread o = tid
    {
        int o = tid;
        float sc, sh;
        bn_coef(bn1, o, 256, sc, sh);
#pragma unroll 1
        for (int chk = 0; chk < 4; chk++) {
            int nb = chk * 16;
            float acc[16];
#pragma unroll
            for (int k = 0; k < 16; k++) acc[k] = 0.f;
#pragma unroll 4
            for (int c = 0; c < 64; c++) {
                float w = w1t[c * 257 + o];
                const float4* f4 = (const float4*)(fs + c * 68 + nb);
                float4 a = f4[0], bb = f4[1], cc = f4[2], dd = f4[3];
                acc[0]  = fmaf(w, a.x, acc[0]);   acc[1]  = fmaf(w, a.y, acc[1]);
                acc[2]  = fmaf(w, a.z, acc[2]);   acc[3]  = fmaf(w, a.w, acc[3]);
                acc[4]  = fmaf(w, bb.x, acc[4]);  acc[5]  = fmaf(w, bb.y, acc[5]);
                acc[6]  = fmaf(w, bb.z, acc[6]);  acc[7]  = fmaf(w, bb.w, acc[7]);
                acc[8]  = fmaf(w, cc.x, acc[8]);  acc[9]  = fmaf(w, cc.y, acc[9]);
                acc[10] = fmaf(w, cc.z, acc[10]); acc[11] = fmaf(w, cc.w, acc[11]);
                acc[12] = fmaf(w, dd.x, acc[12]); acc[13] = fmaf(w, dd.y, acc[13]);
                acc[14] = fmaf(w, dd.z, acc[14]); acc[15] = fmaf(w, dd.w, acc[15]);
            }
#pragma unroll
            for (int k = 0; k < 16; k++) {
                float h = fmaf(acc[k], sc, sh);
                hs[o * 68 + nb + k] = fmaxf(h, 0.f);
            }
        }
    }
    __syncthreads();

    // stage 2: out[c][nn] = relu(bn2(sum_o w2[c][o] h[o][nn]) + f[c][nn])
    {
        int c = tid & 63, g = tid >> 6, nb = g * 16;
        float sc, sh;
        bn_coef(bn2, c, 64, sc, sh);
        float acc[16];
#pragma unroll
        for (int k = 0; k < 16; k++) acc[k] = 0.f;
#pragma unroll 4
        for (int o = 0; o < 256; o++) {
            float w = w2t[o * 65 + c];
            const float4* h4 = (const float4*)(hs + o * 68 + nb);
            float4 a = h4[0], bb = h4[1], cc = h4[2], dd = h4[3];
            acc[0]  = fmaf(w, a.x, acc[0]);   acc[1]  = fmaf(w, a.y, acc[1]);
            acc[2]  = fmaf(w, a.z, acc[2]);   acc[3]  = fmaf(w, a.w, acc[3]);
            acc[4]  = fmaf(w, bb.x, acc[4]);  acc[5]  = fmaf(w, bb.y, acc[5]);
            acc[6]  = fmaf(w, bb.z, acc[6]);  acc[7]  = fmaf(w, bb.w, acc[7]);
            acc[8]  = fmaf(w, cc.x, acc[8]);  acc[9]  = fmaf(w, cc.y, acc[9]);
            acc[10] = fmaf(w, cc.z, acc[10]); acc[11] = fmaf(w, cc.w, acc[11]);
            acc[12] = fmaf(w, dd.x, acc[12]); acc[13] = fmaf(w, dd.y, acc[13]);
            acc[14] = fmaf(w, dd.z, acc[14]); acc[15] = fmaf(w, dd.w, acc[15]);
        }
#pragma unroll
        for (int k = 0; k < 16; k++) {
            int nn = nb + k;
            float r = fmaf(acc[k], sc, sh) + fs[c * 68 + nn];
            fs[c * 68 + nn] = fmaxf(r, 0.f);
        }
    }
    __syncthreads();

    for (int i = tid; i < 4096; i += 256) {
        int c = i >> 6, nn = i & 63;
        out[b * 16384 + c * 256 + n0 + nn] = fs[c * 68 + nn];
    }
}

// ---------------- launch ----------------
extern "C" void kernel_launch(void* const* d_in, const int* in_sizes, int n_in,
                              void* d_out, int out_size) {
    // inputs: x, stroke_idx, [n_strokes scalar?], then 18 weight/param arrays
    int base = (in_sizes[2] == 512) ? 2 : 3;

    const float* x          = (const float*)d_in[0];
    const int*   stroke     = (const int*)d_in[1];
    const float* ga_q_w     = (const float*)d_in[base + 0];
    const float* ga_k_w     = (const float*)d_in[base + 1];
    const float* ga_v_w     = (const float*)d_in[base + 2];
    const float* ga_v_b     = (const float*)d_in[base + 3];
    const float* ga_bn_p    = (const float*)d_in[base + 4];
    const float* ga_lb_w    = (const float*)d_in[base + 5];
    const float* ga_lb_bn_p = (const float*)d_in[base + 6];
    const float* sa_q_w     = (const float*)d_in[base + 7];
    const float* sa_k_w     = (const float*)d_in[base + 8];
    const float* sa_v_w     = (const float*)d_in[base + 9];
    const float* sa_v_b     = (const float*)d_in[base + 10];
    const float* sa_bn_p    = (const float*)d_in[base + 11];
    const float* sa_lb_w    = (const float*)d_in[base + 12];
    const float* sa_lb_bn_p = (const float*)d_in[base + 13];
    const float* mlp_w1     = (const float*)d_in[base + 14];
    const float* mlp_bn1_p  = (const float*)d_in[base + 15];
    const float* mlp_w2     = (const float*)d_in[base + 16];
    const float* mlp_bn2_p  = (const float*)d_in[base + 17];

    cudaFuncSetAttribute(attn_kernel, cudaFuncAttributeMaxDynamicSharedMemorySize, SMEM_A_BYTES);
    cudaFuncSetAttribute(mlp_kernel,  cudaFuncAttributeMaxDynamicSharedMemorySize, SMEM_M_BYTES);

    proj_kernel<<<dim3(64, 2), 128>>>(x, ga_q_w, ga_k_w, ga_v_w, ga_v_b, ga_lb_w,
                                      sa_q_w, sa_k_w, sa_v_w, sa_v_b, sa_lb_w);
    attn_kernel<<<dim3(64, 2), 128, SMEM_A_BYTES>>>(stroke, ga_bn_p, ga_lb_bn_p,
                                                    sa_bn_p, sa_lb_bn_p);
    mlp_kernel<<<dim3(4, 64), 256, SMEM_M_BYTES>>>(mlp_w1, mlp_bn1_p, mlp_w2, mlp_bn2_p,
                                                   (float*)d_out);
}

// round 3
// speedup vs baseline: 1.3387x; 1.3387x over previous
#include <cuda_runtime.h>
#include <math.h>

#define BATCH 64
#define CH    64
#define NPT   256
#define NQK   8
#define NVC   32
#define NSTK  16

typedef unsigned long long u64;

// ---------------- global scratch ----------------
// unified projection scratch: per batch 160 rows x 256 cols
// rows: 0-7 ga_q, 8-15 ga_k, 16-47 ga_v(raw), 48-55 sa_q, 56-63 sa_k,
//       64-95 sa_v(raw), 96-127 ga_lb, 128-159 sa_lb
__device__ float g_proj[BATCH * 160 * NPT];
__device__ float g_f[BATCH * CH * NPT];

// ---------------- f32x2 helpers ----------------
__device__ __forceinline__ u64 f2pack(float a, float b) {
    u64 r;
    asm("mov.b64 %0, {%1, %2};" : "=l"(r) : "r"(__float_as_uint(a)), "r"(__float_as_uint(b)));
    return r;
}
__device__ __forceinline__ u64 ffma2(u64 a, u64 b, u64 c) {
    u64 d;
    asm("fma.rn.f32x2 %0, %1, %2, %3;" : "=l"(d) : "l"(a), "l"(b), "l"(c));
    return d;
}
__device__ __forceinline__ u64 fadd2(u64 a, u64 b) {
    u64 d;
    asm("add.rn.f32x2 %0, %1, %2;" : "=l"(d) : "l"(a), "l"(b));
    return d;
}
__device__ __forceinline__ void unpack2(u64 v, float& lo, float& hi) {
    unsigned int l, h;
    asm("mov.b64 {%0, %1}, %2;" : "=r"(l), "=r"(h) : "l"(v));
    lo = __uint_as_float(l);
    hi = __uint_as_float(h);
}
__device__ __forceinline__ float hsum2(u64 v) {
    float lo, hi;
    unpack2(v, lo, hi);
    return lo + hi;
}

__device__ __forceinline__ void bn_coef(const float* __restrict__ p, int ch, int cn,
                                        float& sc, float& sh) {
    float ga = __ldg(p + ch);
    float be = __ldg(p + cn + ch);
    float mu = __ldg(p + 2 * cn + ch);
    float va = __ldg(p + 3 * cn + ch);
    sc = ga * rsqrtf(va + 1e-5f);
    sh = fmaf(-mu, sc, be);
}

// ---------------- kernel 1: all projections ----------------
// grid (64, 8): y>>1 = output group (40 rows each), y&1 = n half. block 128.
__global__ void proj_kernel(const float* __restrict__ x,
                            const float* __restrict__ ga_q_w, const float* __restrict__ ga_k_w,
                            const float* __restrict__ ga_v_w,
                            const float* __restrict__ ga_lb_w,
                            const float* __restrict__ sa_q_w, const float* __restrict__ sa_k_w,
                            const float* __restrict__ sa_v_w,
                            const float* __restrict__ sa_lb_w) {
    __shared__ float ws[40 * 64];
    int b = blockIdx.x, tid = threadIdx.x;
    int og = blockIdx.y >> 1, nh = blockIdx.y & 1;
    int n = nh * 128 + tid;

    for (int i = tid; i < 2560; i += 128) {
        int r = og * 40 + (i >> 6), c = i & 63;
        float v;
        if      (r < 8)   v = __ldg(&ga_q_w[r * 64 + c]);
        else if (r < 16)  v = __ldg(&ga_k_w[(r - 8) * 64 + c]);
        else if (r < 48)  v = __ldg(&ga_v_w[(r - 16) * 64 + c]);
        else if (r < 56)  v = __ldg(&sa_q_w[(r - 48) * 64 + c]);
        else if (r < 64)  v = __ldg(&sa_k_w[(r - 56) * 64 + c]);
        else if (r < 96)  v = __ldg(&sa_v_w[(r - 64) * 64 + c]);
        else if (r < 128) v = __ldg(&ga_lb_w[(r - 96) * 64 + c]);
        else              v = __ldg(&sa_lb_w[(r - 128) * 64 + c]);
        ws[i] = v;
    }
    __syncthreads();

    u64 xr2[32];
#pragma unroll
    for (int c = 0; c < 32; c++) {
        float a = __ldg(&x[b * 16384 + (2 * c) * 256 + n]);
        float bb = __ldg(&x[b * 16384 + (2 * c + 1) * 256 + n]);
        xr2[c] = f2pack(a, bb);
    }

    float* outp = g_proj + (b * 160 + og * 40) * 256 + n;
#pragma unroll 2
    for (int o = 0; o < 40; o++) {
        const ulonglong2* w2 = (const ulonglong2*)(ws + o * 64);
        u64 a0 = 0ULL, a1 = 0ULL;
#pragma unroll
        for (int i = 0; i < 16; i++) {
            ulonglong2 wv = w2[i];
            a0 = ffma2(wv.x, xr2[2 * i], a0);
            a1 = ffma2(wv.y, xr2[2 * i + 1], a1);
        }
        outp[o * 256] = hsum2(fadd2(a0, a1));
    }
}

// ---------------- kernel 2: attention (one branch per block) ----------------
// grid (64, 4): y>>1 = branch (0=GA, 1=SA), y&1 = row half. block 128.
#define ATTN_SMEM_FLOATS (2048 + 9216 + 2048 + 256)
#define ATTN_SMEM_BYTES  (ATTN_SMEM_FLOATS * 4)

__global__ void attn_kernel(const int* __restrict__ stroke_idx,
                            const float* __restrict__ ga_v_b, const float* __restrict__ sa_v_b,
                            const float* __restrict__ ga_bn_p, const float* __restrict__ ga_lb_bn_p,
                            const float* __restrict__ sa_bn_p, const float* __restrict__ sa_lb_bn_p) {
    extern __shared__ float sm[];
    float* Ks   = sm;                  // [m*8 + j]
    float* Vs   = sm + 2048;           // [m*36 + o], pad 4
    float* bins = sm + 2048 + 9216;    // [s*128 + tid]
    int*   stk  = (int*)(sm + 2048 + 9216 + 2048);

    int b = blockIdx.x, tid = threadIdx.x;
    int branch = blockIdx.y >> 1, half = blockIdx.y & 1;
    int n = half * 128 + tid;

    int qbase  = branch ? 48 : 0;
    int kbase  = qbase + 8;
    int vbase  = branch ? 64 : 16;
    int lbbase = branch ? 128 : 96;
    const float* vb = branch ? sa_v_b : ga_v_b;
    const float* gp = g_proj + b * 160 * 256;

    for (int i = tid; i < 2048; i += 128) {
        int r = i >> 8, m = i & 255;
        Ks[m * 8 + r] = gp[(kbase + r) * 256 + m];
    }
    for (int i = tid; i < 8192; i += 128) {
        int r = i >> 8, m = i & 255;
        Vs[m * 36 + r] = gp[(vbase + r) * 256 + m] + __ldg(vb + r);
    }
    if (branch)
        for (int i = tid; i < 256; i += 128) stk[i] = stroke_idx[b * 256 + i];
    __syncthreads();

    u64 q2[4];
#pragma unroll
    for (int j = 0; j < 4; j++)
        q2[j] = f2pack(gp[(qbase + 2 * j) * 256 + n], gp[(qbase + 2 * j + 1) * 256 + n]);

    const float INV_GA = 0.35355339059327373f;   // 1/sqrt(8)
    const float ESC    = 3.5355339059327378f;    // 10/sqrt(8)

    // ---- max pass ----
    float mx = -1e30f;
#pragma unroll 4
    for (int m = 0; m < 256; m++) {
        const ulonglong2* k2 = (const ulonglong2*)(Ks + m * 8);
        ulonglong2 ka = k2[0], kb = k2[1];
        u64 d0 = ffma2(q2[0], ka.x, 0ULL);
        d0 = ffma2(q2[1], ka.y, d0);
        d0 = ffma2(q2[2], kb.x, d0);
        d0 = ffma2(q2[3], kb.y, d0);
        mx = fmaxf(mx, hsum2(d0));
    }

    u64 o2[16];
#pragma unroll
    for (int v = 0; v < 16; v++) o2[v] = 0ULL;

    if (branch == 0) {
        // ---- GA: softmax + attn @ V ----
        float sum = 0.f;
#pragma unroll 2
        for (int m = 0; m < 256; m++) {
            const ulonglong2* k2 = (const ulonglong2*)(Ks + m * 8);
            ulonglong2 ka = k2[0], kb = k2[1];
            u64 d0 = ffma2(q2[0], ka.x, 0ULL);
            d0 = ffma2(q2[1], ka.y, d0);
            d0 = ffma2(q2[2], kb.x, d0);
            d0 = ffma2(q2[3], kb.y, d0);
            float e = __expf((hsum2(d0) - mx) * INV_GA);
            sum += e;
            u64 ep = f2pack(e, e);
            const ulonglong2* v2p = (const ulonglong2*)(Vs + m * 36);
#pragma unroll
            for (int g = 0; g < 8; g++) {
                ulonglong2 vv = v2p[g];
                o2[2 * g]     = ffma2(ep, vv.x, o2[2 * g]);
                o2[2 * g + 1] = ffma2(ep, vv.y, o2[2 * g + 1]);
            }
        }
        float rcp = 1.f / sum;
#pragma unroll
        for (int g = 0; g < 16; g++) {
            float v0, v1;
            unpack2(o2[g], v0, v1);
            int ch0 = 2 * g;
            float sc1, sh1, sc2, sh2;
            bn_coef(ga_bn_p, ch0, 32, sc1, sh1);
            bn_coef(ga_lb_bn_p, ch0, 32, sc2, sh2);
            float lb0 = gp[(lbbase + ch0) * 256 + n];
            g_f[b * 16384 + ch0 * 256 + n] = fmaf(v0 * rcp, sc1, sh1) + fmaf(lb0, sc2, sh2);
            bn_coef(ga_bn_p, ch0 + 1, 32, sc1, sh1);
            bn_coef(ga_lb_bn_p, ch0 + 1, 32, sc2, sh2);
            float lb1 = gp[(lbbase + ch0 + 1) * 256 + n];
            g_f[b * 16384 + (ch0 + 1) * 256 + n] = fmaf(v1 * rcp, sc1, sh1) + fmaf(lb1, sc2, sh2);
        }
    } else {
        // ---- SA: collapsed 16-stroke masked softmax sum ----
        const float CC  = 1.00001000005f;
        const float CM1 = 1.00000500002e-05f;
#pragma unroll
        for (int s = 0; s < 16; s++) bins[s * 128 + tid] = 0.f;
        float E = 0.f;
#pragma unroll 2
        for (int m = 0; m < 256; m++) {
            const ulonglong2* k2 = (const ulonglong2*)(Ks + m * 8);
            ulonglong2 ka = k2[0], kb = k2[1];
            u64 d0 = ffma2(q2[0], ka.x, 0ULL);
            d0 = ffma2(q2[1], ka.y, d0);
            d0 = ffma2(q2[2], kb.x, d0);
            d0 = ffma2(q2[3], kb.y, d0);
            float e = __expf((hsum2(d0) - mx) * ESC);
            E += e;
            bins[stk[m] * 128 + tid] += e;
        }
        float Sinv = 0.f;
#pragma unroll
        for (int s = 0; s < 16; s++) {
            float z = fmaf(-CM1, bins[s * 128 + tid], CC * E);
            float zi = 1.f / z;
            bins[s * 128 + tid] = zi;
            Sinv += zi;
        }
#pragma unroll
        for (int s = 0; s < 16; s++)
            bins[s * 128 + tid] = fmaf(-CM1, bins[s * 128 + tid], CC * Sinv);

#pragma unroll 2
        for (int m = 0; m < 256; m++) {
            const ulonglong2* k2 = (const ulonglong2*)(Ks + m * 8);
            ulonglong2 ka = k2[0], kb = k2[1];
            u64 d0 = ffma2(q2[0], ka.x, 0ULL);
            d0 = ffma2(q2[1], ka.y, d0);
            d0 = ffma2(q2[2], kb.x, d0);
            d0 = ffma2(q2[3], kb.y, d0);
            float e = __expf((hsum2(d0) - mx) * ESC);
            float w = e * bins[stk[m] * 128 + tid];
            u64 wp = f2pack(w, w);
            const ulonglong2* v2p = (const ulonglong2*)(Vs + m * 36);
#pragma unroll
            for (int g = 0; g < 8; g++) {
                ulonglong2 vv = v2p[g];
                o2[2 * g]     = ffma2(wp, vv.x, o2[2 * g]);
                o2[2 * g + 1] = ffma2(wp, vv.y, o2[2 * g + 1]);
            }
        }
#pragma unroll
        for (int g = 0; g < 16; g++) {
            float v0, v1;
            unpack2(o2[g], v0, v1);
            int ch0 = 2 * g;
            float sc1, sh1, sc2, sh2;
            bn_coef(sa_bn_p, ch0, 32, sc1, sh1);
            bn_coef(sa_lb_bn_p, ch0, 32, sc2, sh2);
            float lb0 = gp[(lbbase + ch0) * 256 + n];
            g_f[b * 16384 + (32 + ch0) * 256 + n] = fmaf(v0, sc1, sh1) + fmaf(lb0, sc2, sh2);
            bn_coef(sa_bn_p, ch0 + 1, 32, sc1, sh1);
            bn_coef(sa_lb_bn_p, ch0 + 1, 32, sc2, sh2);
            float lb1 = gp[(lbbase + ch0 + 1) * 256 + n];
            g_f[b * 16384 + (32 + ch0 + 1) * 256 + n] = fmaf(v1, sc1, sh1) + fmaf(lb1, sc2, sh2);
        }
    }
}

// ---------------- kernel 3: MLP ----------------
// grid (4, 64), block 256. ~219 KB dyn smem.
#define FS_OFF   0
#define W1T_OFF  4352                   // fs = 64*68
#define W2T_OFF  (4352 + 16448)         // w1t = 64*257
#define HS_OFF   (4352 + 16448 + 16640) // w2t = 256*65
#define SMEM_M_BYTES ((4352 + 16448 + 16640 + 17408) * 4)

__global__ void mlp_kernel(const float* __restrict__ w1, const float* __restrict__ bn1,
                           const float* __restrict__ w2, const float* __restrict__ bn2,
                           float* __restrict__ out) {
    extern __shared__ float sm[];
    float* fs  = sm + FS_OFF;
    float* w1t = sm + W1T_OFF;
    float* w2t = sm + W2T_OFF;
    float* hs  = sm + HS_OFF;

    int b = blockIdx.y, n0 = blockIdx.x * 64, tid = threadIdx.x;

    for (int i = tid; i < 4096; i += 256) {
        int c = i >> 6, nn = i & 63;
        fs[c * 68 + nn] = g_f[b * 16384 + c * 256 + n0 + nn];
    }
    for (int i = tid; i < 16384; i += 256) {        // w1 [256,64] -> w1t[c][o]
        int o = i >> 6, c = i & 63;
        w1t[c * 257 + o] = __ldg(&w1[i]);
    }
    for (int i = tid; i < 16384; i += 256) {        // w2 [64,256] -> w2t[o][c]
        int c = i >> 8, o = i & 255;
        w2t[o * 65 + c] = __ldg(&w2[i]);
    }
    __syncthreads();

    // stage 1: 4 outputs x 16 cols per thread
    {
        int og = tid >> 2, nc = tid & 3;
        int o0 = og * 4, nb = nc * 16;
        u64 acc[4][8];
#pragma unroll
        for (int j = 0; j < 4; j++)
#pragma unroll
            for (int k = 0; k < 8; k++) acc[j][k] = 0ULL;

#pragma unroll 2
        for (int c = 0; c < 64; c++) {
            const ulonglong2* f2p = (const ulonglong2*)(fs + c * 68 + nb);
            u64 xv[8];
#pragma unroll
            for (int g = 0; g < 4; g++) {
                ulonglong2 t = f2p[g];
                xv[2 * g] = t.x;
                xv[2 * g + 1] = t.y;
            }
            u64 w[4];
#pragma unroll
            for (int j = 0; j < 4; j++) {
                float wv = w1t[c * 257 + o0 + j];
                w[j] = f2pack(wv, wv);
            }
#pragma unroll
            for (int j = 0; j < 4; j++)
#pragma unroll
                for (int k = 0; k < 8; k++)
                    acc[j][k] = ffma2(w[j], xv[k], acc[j][k]);
        }
#pragma unroll
        for (int j = 0; j < 4; j++) {
            float sc, sh;
            bn_coef(bn1, o0 + j, 256, sc, sh);
            float* hrow = hs + (o0 + j) * 68 + nb;
#pragma unroll
            for (int k = 0; k < 8; k++) {
                float v0, v1;
                unpack2(acc[j][k], v0, v1);
                hrow[2 * k]     = fmaxf(fmaf(v0, sc, sh), 0.f);
                hrow[2 * k + 1] = fmaxf(fmaf(v1, sc, sh), 0.f);
            }
        }
    }
    __syncthreads();

    // stage 2: 1 output x 16 cols per thread
    {
        int c = tid & 63, nb = (tid >> 6) * 16;
        float sc, sh;
        bn_coef(bn2, c, 64, sc, sh);
        u64 acc[8];
#pragma unroll
        for (int k = 0; k < 8; k++) acc[k] = 0ULL;
#pragma unroll 2
        for (int o = 0; o < 256; o++) {
            float wv = w2t[o * 65 + c];
            u64 w = f2pack(wv, wv);
            const ulonglong2* h2 = (const ulonglong2*)(hs + o * 68 + nb);
#pragma unroll
            for (int g = 0; g < 4; g++) {
                ulonglong2 t = h2[g];
                acc[2 * g]     = ffma2(w, t.x, acc[2 * g]);
                acc[2 * g + 1] = ffma2(w, t.y, acc[2 * g + 1]);
            }
        }
        float res[16];
#pragma unroll
        for (int k = 0; k < 8; k++) {
            float v0, v1;
            unpack2(acc[k], v0, v1);
            res[2 * k] = v0;
            res[2 * k + 1] = v1;
        }
        __syncthreads();   // ensure stage-1 hs reads done before fs overwrite? (fs untouched; sync for safety of reuse below)
#pragma unroll
        for (int k = 0; k < 16; k++) {
            int nn = nb + k;
            float r = fmaf(res[k], sc, sh) + fs[c * 68 + nn];
            fs[c * 68 + nn] = fmaxf(r, 0.f);
        }
    }
    __syncthreads();

    for (int i = tid; i < 4096; i += 256) {
        int c = i >> 6, nn = i & 63;
        out[b * 16384 + c * 256 + n0 + nn] = fs[c * 68 + nn];
    }
}

// ---------------- launch ----------------
extern "C" void kernel_launch(void* const* d_in, const int* in_sizes, int n_in,
                              void* d_out, int out_size) {
    int base = (in_sizes[2] == 512) ? 2 : 3;

    const float* x          = (const float*)d_in[0];
    const int*   stroke     = (const int*)d_in[1];
    const float* ga_q_w     = (const float*)d_in[base + 0];
    const float* ga_k_w     = (const float*)d_in[base + 1];
    const float* ga_v_w     = (const float*)d_in[base + 2];
    const float* ga_v_b     = (const float*)d_in[base + 3];
    const float* ga_bn_p    = (const float*)d_in[base + 4];
    const float* ga_lb_w    = (const float*)d_in[base + 5];
    const float* ga_lb_bn_p = (const float*)d_in[base + 6];
    const float* sa_q_w     = (const float*)d_in[base + 7];
    const float* sa_k_w     = (const float*)d_in[base + 8];
    const float* sa_v_w     = (const float*)d_in[base + 9];
    const float* sa_v_b     = (const float*)d_in[base + 10];
    const float* sa_bn_p    = (const float*)d_in[base + 11];
    const float* sa_lb_w    = (const float*)d_in[base + 12];
    const float* sa_lb_bn_p = (const float*)d_in[base + 13];
    const float* mlp_w1     = (const float*)d_in[base + 14];
    const float* mlp_bn1_p  = (const float*)d_in[base + 15];
    const float* mlp_w2     = (const float*)d_in[base + 16];
    const float* mlp_bn2_p  = (const float*)d_in[base + 17];

    cudaFuncSetAttribute(attn_kernel, cudaFuncAttributeMaxDynamicSharedMemorySize, ATTN_SMEM_BYTES);
    cudaFuncSetAttribute(mlp_kernel,  cudaFuncAttributeMaxDynamicSharedMemorySize, SMEM_M_BYTES);

    proj_kernel<<<dim3(64, 8), 128>>>(x, ga_q_w, ga_k_w, ga_v_w, ga_lb_w,
                                      sa_q_w, sa_k_w, sa_v_w, sa_lb_w);
    attn_kernel<<<dim3(64, 4), 128, ATTN_SMEM_BYTES>>>(stroke, ga_v_b, sa_v_b,
                                                       ga_bn_p, ga_lb_bn_p,
                                                       sa_bn_p, sa_lb_bn_p);
    mlp_kernel<<<dim3(4, 64), 256, SMEM_M_BYTES>>>(mlp_w1, mlp_bn1_p, mlp_w2, mlp_bn2_p,
                                                   (float*)d_out);
}

// round 5
// speedup vs baseline: 1.4755x; 1.1022x over previous
#include <cuda_runtime.h>
#include <math.h>

#define BATCH 64
#define CH    64
#define NPT   256

typedef unsigned long long u64;

// ---------------- global scratch ----------------
// g_proj rows per batch: 0-7 ga_q, 8-15 ga_k, 16-47 ga_v(raw), 48-55 sa_q,
// 56-63 sa_k, 64-95 sa_v(raw), 96-127 ga_lb, 128-159 sa_lb
__device__ float g_proj[BATCH * 160 * NPT];
__device__ float g_f[BATCH * CH * NPT];
__device__ float g_h[BATCH * 256 * NPT];   // MLP hidden, 16 MB (L2-resident)

// ---------------- f32x2 helpers ----------------
__device__ __forceinline__ u64 f2pack(float a, float b) {
    u64 r;
    asm("mov.b64 %0, {%1, %2};" : "=l"(r) : "r"(__float_as_uint(a)), "r"(__float_as_uint(b)));
    return r;
}
__device__ __forceinline__ u64 ffma2(u64 a, u64 b, u64 c) {
    u64 d;
    asm("fma.rn.f32x2 %0, %1, %2, %3;" : "=l"(d) : "l"(a), "l"(b), "l"(c));
    return d;
}
__device__ __forceinline__ u64 fadd2(u64 a, u64 b) {
    u64 d;
    asm("add.rn.f32x2 %0, %1, %2;" : "=l"(d) : "l"(a), "l"(b));
    return d;
}
__device__ __forceinline__ void unpack2(u64 v, float& lo, float& hi) {
    unsigned int l, h;
    asm("mov.b64 {%0, %1}, %2;" : "=r"(l), "=r"(h) : "l"(v));
    lo = __uint_as_float(l);
    hi = __uint_as_float(h);
}
__device__ __forceinline__ float hsum2(u64 v) {
    float lo, hi;
    unpack2(v, lo, hi);
    return lo + hi;
}
__device__ __forceinline__ void bn_coef(const float* __restrict__ p, int ch, int cn,
                                        float& sc, float& sh) {
    float ga = __ldg(p + ch);
    float be = __ldg(p + cn + ch);
    float mu = __ldg(p + 2 * cn + ch);
    float va = __ldg(p + 3 * cn + ch);
    sc = ga * rsqrtf(va + 1e-5f);
    sh = fmaf(-mu, sc, be);
}

// ---------------- kernel 1: projections ----------------
// grid (64, 16): y>>1 = out group (20 rows), y&1 = n half. block 128.
__global__ void proj_kernel(const float* __restrict__ x,
                            const float* __restrict__ ga_q_w, const float* __restrict__ ga_k_w,
                            const float* __restrict__ ga_v_w, const float* __restrict__ ga_lb_w,
                            const float* __restrict__ sa_q_w, const float* __restrict__ sa_k_w,
                            const float* __restrict__ sa_v_w, const float* __restrict__ sa_lb_w) {
    __shared__ float ws[20 * 64];
    int b = blockIdx.x, tid = threadIdx.x;
    int og = blockIdx.y >> 1, nh = blockIdx.y & 1;
    int n = nh * 128 + tid;

    for (int i = tid; i < 1280; i += 128) {
        int r = og * 20 + (i >> 6), c = i & 63;
        float v;
        if      (r < 8)   v = __ldg(&ga_q_w[r * 64 + c]);
        else if (r < 16)  v = __ldg(&ga_k_w[(r - 8) * 64 + c]);
        else if (r < 48)  v = __ldg(&ga_v_w[(r - 16) * 64 + c]);
        else if (r < 56)  v = __ldg(&sa_q_w[(r - 48) * 64 + c]);
        else if (r < 64)  v = __ldg(&sa_k_w[(r - 56) * 64 + c]);
        else if (r < 96)  v = __ldg(&sa_v_w[(r - 64) * 64 + c]);
        else if (r < 128) v = __ldg(&ga_lb_w[(r - 96) * 64 + c]);
        else              v = __ldg(&sa_lb_w[(r - 128) * 64 + c]);
        ws[i] = v;
    }
    __syncthreads();

    u64 xr2[32];
#pragma unroll
    for (int c = 0; c < 32; c++) {
        float a = __ldg(&x[b * 16384 + (2 * c) * 256 + n]);
        float bb = __ldg(&x[b * 16384 + (2 * c + 1) * 256 + n]);
        xr2[c] = f2pack(a, bb);
    }

    float* outp = g_proj + (b * 160 + og * 20) * 256 + n;
#pragma unroll 2
    for (int o = 0; o < 20; o++) {
        const ulonglong2* w2 = (const ulonglong2*)(ws + o * 64);
        u64 a0 = 0ULL, a1 = 0ULL;
#pragma unroll
        for (int i = 0; i < 16; i++) {
            ulonglong2 wv = w2[i];
            a0 = ffma2(wv.x, xr2[2 * i], a0);
            a1 = ffma2(wv.y, xr2[2 * i + 1], a1);
        }
        outp[o * 256] = hsum2(fadd2(a0, a1));
    }
}

// ---------------- kernel 2: attention ----------------
// grid (64, 4): y>>1 = branch, y&1 = row half. block 256 = 128 rows x 2 m-halves.
#define KS_OFF  0
#define VS_OFF  2048
#define MB_OFF  11264     // 4352 floats: SA bins (16x256) / V-merge (128x17 u64)
#define MX_OFF  15616
#define EB_OFF  15872
#define STK_OFF 16128
#define ATTN_SMEM_BYTES (16384 * 4)

__global__ void attn_kernel(const int* __restrict__ stroke_idx,
                            const float* __restrict__ ga_v_b, const float* __restrict__ sa_v_b,
                            const float* __restrict__ ga_bn_p, const float* __restrict__ ga_lb_bn_p,
                            const float* __restrict__ sa_bn_p, const float* __restrict__ sa_lb_bn_p) {
    extern __shared__ float sm[];
    float* Ks   = sm + KS_OFF;     // [m*8 + j]
    float* Vs   = sm + VS_OFF;     // [m*36 + o]
    float* MB   = sm + MB_OFF;     // bins [s*256+tid] then V-merge
    float* MX   = sm + MX_OFF;
    float* EB   = sm + EB_OFF;
    int*   stk  = (int*)(sm + STK_OFF);

    int b = blockIdx.x, tid = threadIdx.x;
    int branch = blockIdx.y >> 1, rh = blockIdx.y & 1;
    int row = tid & 127, mh = tid >> 7;
    int n = rh * 128 + row;
    int m0 = mh * 128;

    int qbase  = branch ? 48 : 0;
    int kbase  = qbase + 8;
    int vbase  = branch ? 64 : 16;
    int lbbase = branch ? 128 : 96;
    const float* vb = branch ? sa_v_b : ga_v_b;
    const float* gp = g_proj + b * 160 * 256;

    for (int i = tid; i < 2048; i += 256) {
        int r = i >> 8, m = i & 255;
        Ks[m * 8 + r] = gp[(kbase + r) * 256 + m];
    }
    for (int i = tid; i < 8192; i += 256) {
        int r = i >> 8, m = i & 255;
        Vs[m * 36 + r] = gp[(vbase + r) * 256 + m] + __ldg(vb + r);
    }
    if (branch)
        for (int i = tid; i < 256; i += 256) stk[i] = stroke_idx[b * 256 + i];
    __syncthreads();

    u64 q2[4];
#pragma unroll
    for (int j = 0; j < 4; j++)
        q2[j] = f2pack(gp[(qbase + 2 * j) * 256 + n], gp[(qbase + 2 * j + 1) * 256 + n]);

    const float INV_GA = 0.35355339059327373f;   // 1/sqrt(8)
    const float ESC    = 3.5355339059327378f;    // 10/sqrt(8)

    // ---- max over own m half, then partner merge ----
    float mxl = -1e30f;
#pragma unroll 4
    for (int m = m0; m < m0 + 128; m++) {
        const ulonglong2* k2 = (const ulonglong2*)(Ks + m * 8);
        ulonglong2 ka = k2[0], kb = k2[1];
        u64 d0 = ffma2(q2[0], ka.x, 0ULL);
        d0 = ffma2(q2[1], ka.y, d0);
        d0 = ffma2(q2[2], kb.x, d0);
        d0 = ffma2(q2[3], kb.y, d0);
        mxl = fmaxf(mxl, hsum2(d0));
    }
    MX[tid] = mxl;
    __syncthreads();
    float mx = fmaxf(MX[row], MX[row + 128]);

    u64 o2[16];
#pragma unroll
    for (int v = 0; v < 16; v++) o2[v] = 0ULL;
    u64* mb64 = (u64*)MB;

    if (branch == 0) {
        // ---- GA ----
        float sum = 0.f;
#pragma unroll 2
        for (int m = m0; m < m0 + 128; m++) {
            const ulonglong2* k2 = (const ulonglong2*)(Ks + m * 8);
            ulonglong2 ka = k2[0], kb = k2[1];
            u64 d0 = ffma2(q2[0], ka.x, 0ULL);
            d0 = ffma2(q2[1], ka.y, d0);
            d0 = ffma2(q2[2], kb.x, d0);
            d0 = ffma2(q2[3], kb.y, d0);
            float e = __expf((hsum2(d0) - mx) * INV_GA);
            sum += e;
            u64 ep = f2pack(e, e);
            const ulonglong2* v2p = (const ulonglong2*)(Vs + m * 36);
#pragma unroll
            for (int g = 0; g < 8; g++) {
                ulonglong2 vv = v2p[g];
                o2[2 * g]     = ffma2(ep, vv.x, o2[2 * g]);
                o2[2 * g + 1] = ffma2(ep, vv.y, o2[2 * g + 1]);
            }
        }
        EB[tid] = sum;
        __syncthreads();
        float sumt = EB[row] + EB[row + 128];
        if (mh == 1) {
#pragma unroll
            for (int j = 0; j < 16; j++) mb64[row * 17 + j] = o2[j];
        }
        __syncthreads();
        if (mh == 0) {
            float rcp = 1.f / sumt;
#pragma unroll
            for (int g = 0; g < 16; g++) {
                o2[g] = fadd2(o2[g], mb64[row * 17 + g]);
                float v0, v1;
                unpack2(o2[g], v0, v1);
                int c0 = 2 * g;
                float sc1, sh1, sc2, sh2;
                bn_coef(ga_bn_p, c0, 32, sc1, sh1);
                bn_coef(ga_lb_bn_p, c0, 32, sc2, sh2);
                float lb0 = gp[(lbbase + c0) * 256 + n];
                g_f[b * 16384 + c0 * 256 + n] = fmaf(v0 * rcp, sc1, sh1) + fmaf(lb0, sc2, sh2);
                bn_coef(ga_bn_p, c0 + 1, 32, sc1, sh1);
                bn_coef(ga_lb_bn_p, c0 + 1, 32, sc2, sh2);
                float lb1 = gp[(lbbase + c0 + 1) * 256 + n];
                g_f[b * 16384 + (c0 + 1) * 256 + n] = fmaf(v1 * rcp, sc1, sh1) + fmaf(lb1, sc2, sh2);
            }
        }
    } else {
        // ---- SA: collapsed 16-stroke masked softmax sum ----
        const float CC  = 1.00001000005f;
        const float CM1 = 1.00000500002e-05f;
#pragma unroll
        for (int s = 0; s < 16; s++) MB[s * 256 + tid] = 0.f;
        __syncthreads();
        float E = 0.f;
#pragma unroll 2
        for (int m = m0; m < m0 + 128; m++) {
            const ulonglong2* k2 = (const ulonglong2*)(Ks + m * 8);
            ulonglong2 ka = k2[0], kb = k2[1];
            u64 d0 = ffma2(q2[0], ka.x, 0ULL);
            d0 = ffma2(q2[1], ka.y, d0);
            d0 = ffma2(q2[2], kb.x, d0);
            d0 = ffma2(q2[3], kb.y, d0);
            float e = __expf((hsum2(d0) - mx) * ESC);
            E += e;
            MB[stk[m] * 256 + tid] += e;
        }
        EB[tid] = E;
        __syncthreads();
        if (mh == 0) {
            float Et = EB[row] + EB[row + 128];
            float zi[16];
            float Sinv = 0.f;
#pragma unroll
            for (int s = 0; s < 16; s++) {
                float bsum = MB[s * 256 + row] + MB[s * 256 + row + 128];
                float z = fmaf(-CM1, bsum, CC * Et);
                zi[s] = 1.f / z;
                Sinv += zi[s];
            }
#pragma unroll
            for (int s = 0; s < 16; s++)
                MB[s * 256 + row] = fmaf(-CM1, zi[s], CC * Sinv);   // coef_s
        }
        __syncthreads();
#pragma unroll 2
        for (int m = m0; m < m0 + 128; m++) {
            const ulonglong2* k2 = (const ulonglong2*)(Ks + m * 8);
            ulonglong2 ka = k2[0], kb = k2[1];
            u64 d0 = ffma2(q2[0], ka.x, 0ULL);
            d0 = ffma2(q2[1], ka.y, d0);
            d0 = ffma2(q2[2], kb.x, d0);
            d0 = ffma2(q2[3], kb.y, d0);
            float e = __expf((hsum2(d0) - mx) * ESC);
            float w = e * MB[stk[m] * 256 + row];
            u64 wp = f2pack(w, w);
            const ulonglong2* v2p = (const ulonglong2*)(Vs + m * 36);
#pragma unroll
            for (int g = 0; g < 8; g++) {
                ulonglong2 vv = v2p[g];
                o2[2 * g]     = ffma2(wp, vv.x, o2[2 * g]);
                o2[2 * g + 1] = ffma2(wp, vv.y, o2[2 * g + 1]);
            }
        }
        __syncthreads();   // bins done; reuse MB for V merge
        if (mh == 1) {
#pragma unroll
            for (int j = 0; j < 16; j++) mb64[row * 17 + j] = o2[j];
        }
        __syncthreads();
        if (mh == 0) {
#pragma unroll
            for (int g = 0; g < 16; g++) {
                o2[g] = fadd2(o2[g], mb64[row * 17 + g]);
                float v0, v1;
                unpack2(o2[g], v0, v1);
                int c0 = 2 * g;
                float sc1, sh1, sc2, sh2;
                bn_coef(sa_bn_p, c0, 32, sc1, sh1);
                bn_coef(sa_lb_bn_p, c0, 32, sc2, sh2);
                float lb0 = gp[(lbbase + c0) * 256 + n];
                g_f[b * 16384 + (32 + c0) * 256 + n] = fmaf(v0, sc1, sh1) + fmaf(lb0, sc2, sh2);
                bn_coef(sa_bn_p, c0 + 1, 32, sc1, sh1);
                bn_coef(sa_lb_bn_p, c0 + 1, 32, sc2, sh2);
                float lb1 = gp[(lbbase + c0 + 1) * 256 + n];
                g_f[b * 16384 + (32 + c0 + 1) * 256 + n] = fmaf(v1, sc1, sh1) + fmaf(lb1, sc2, sh2);
            }
        }
    }
}

// ---------------- kernel 3a: MLP stage 1 (h = relu(bn1(w1@f))) ----------------
// grid (8, 64): bx>>1 = ch chunk (64 of 256), bx&1 = col chunk (128). block 256.
#define M1_W_OFF 0
#define M1_F_OFF 4352                       // w1s = 64*68
#define M1_SMEM_BYTES ((4352 + 8448) * 4)   // + fs = 64*132

__global__ void mlp1_kernel(const float* __restrict__ w1, const float* __restrict__ bn1) {
    extern __shared__ float sm[];
    float* w1s = sm + M1_W_OFF;   // [k*68 + o]
    float* fs  = sm + M1_F_OFF;   // [k*132 + col]

    int b = blockIdx.y, tid = threadIdx.x;
    int cc = blockIdx.x >> 1, nc = blockIdx.x & 1;
    int tx = tid & 31, ty = tid >> 5;

    for (int i = tid; i < 4096; i += 256) {
        int o = i >> 6, k = i & 63;
        w1s[k * 68 + o] = __ldg(&w1[(cc * 64 + o) * 64 + k]);
    }
    for (int i = tid; i < 8192; i += 256) {
        int k = i >> 7, col = i & 127;
        fs[k * 132 + col] = g_f[b * 16384 + k * 256 + nc * 128 + col];
    }
    __syncthreads();

    // thread tile: 8 ch (4 pairs) x 4 cols
    u64 acc[4][4];
#pragma unroll
    for (int p = 0; p < 4; p++)
#pragma unroll
        for (int c = 0; c < 4; c++) acc[p][c] = 0ULL;

#pragma unroll 4
    for (int k = 0; k < 64; k++) {
        const ulonglong2* wv2 = (const ulonglong2*)(w1s + k * 68 + ty * 8);
        ulonglong2 wa = wv2[0], wb = wv2[1];            // ch pairs (0,1),(2,3)
        float4 hv = *(const float4*)(fs + k * 132 + tx * 4);
        u64 h0 = f2pack(hv.x, hv.x), h1 = f2pack(hv.y, hv.y);
        u64 h2 = f2pack(hv.z, hv.z), h3 = f2pack(hv.w, hv.w);
        acc[0][0] = ffma2(wa.x, h0, acc[0][0]);
        acc[0][1] = ffma2(wa.x, h1, acc[0][1]);
        acc[0][2] = ffma2(wa.x, h2, acc[0][2]);
        acc[0][3] = ffma2(wa.x, h3, acc[0][3]);
        acc[1][0] = ffma2(wa.y, h0, acc[1][0]);
        acc[1][1] = ffma2(wa.y, h1, acc[1][1]);
        acc[1][2] = ffma2(wa.y, h2, acc[1][2]);
        acc[1][3] = ffma2(wa.y, h3, acc[1][3]);
        acc[2][0] = ffma2(wb.x, h0, acc[2][0]);
        acc[2][1] = ffma2(wb.x, h1, acc[2][1]);
        acc[2][2] = ffma2(wb.x, h2, acc[2][2]);
        acc[2][3] = ffma2(wb.x, h3, acc[2][3]);
        acc[3][0] = ffma2(wb.y, h0, acc[3][0]);
        acc[3][1] = ffma2(wb.y, h1, acc[3][1]);
        acc[3][2] = ffma2(wb.y, h2, acc[3][2]);
        acc[3][3] = ffma2(wb.y, h3, acc[3][3]);
    }

    int n0 = nc * 128 + tx * 4;
#pragma unroll
    for (int p = 0; p < 4; p++) {
        int ch0 = cc * 64 + ty * 8 + 2 * p;
        float sc0, sh0, sc1s, sh1s;
        bn_coef(bn1, ch0, 256, sc0, sh0);
        bn_coef(bn1, ch0 + 1, 256, sc1s, sh1s);
        float4 r0, r1;
        float a, bb;
        unpack2(acc[p][0], a, bb); r0.x = fmaxf(fmaf(a, sc0, sh0), 0.f); r1.x = fmaxf(fmaf(bb, sc1s, sh1s), 0.f);
        unpack2(acc[p][1], a, bb); r0.y = fmaxf(fmaf(a, sc0, sh0), 0.f); r1.y = fmaxf(fmaf(bb, sc1s, sh1s), 0.f);
        unpack2(acc[p][2], a, bb); r0.z = fmaxf(fmaf(a, sc0, sh0), 0.f); r1.z = fmaxf(fmaf(bb, sc1s, sh1s), 0.f);
        unpack2(acc[p][3], a, bb); r0.w = fmaxf(fmaf(a, sc0, sh0), 0.f); r1.w = fmaxf(fmaf(bb, sc1s, sh1s), 0.f);
        *(float4*)&g_h[b * 65536 + ch0 * 256 + n0]       = r0;
        *(float4*)&g_h[b * 65536 + (ch0 + 1) * 256 + n0] = r1;
    }
}

// ---------------- kernel 3b: MLP stage 2 (out = relu(bn2(w2@h)+f)) ----------------
// grid (4, 64): bx = col chunk (64). block 256.
#define M2_W_OFF 0
#define M2_H_OFF 4352                       // ws = 64*68
#define M2_SMEM_BYTES ((4352 + 4352) * 4)   // + hs = 64*68

__global__ void mlp2_kernel(const float* __restrict__ w2, const float* __restrict__ bn2,
                            float* __restrict__ out) {
    extern __shared__ float sm[];
    float* ws = sm + M2_W_OFF;   // [k*68 + c]
    float* hs = sm + M2_H_OFF;   // [k*68 + col]

    int b = blockIdx.y, tid = threadIdx.x;
    int n0b = blockIdx.x * 64;
    int tx = tid & 15, ty = tid >> 4;

    // thread tile: 4 ch (2 pairs) x 4 cols
    u64 acc[2][4];
#pragma unroll
    for (int p = 0; p < 2; p++)
#pragma unroll
        for (int c = 0; c < 4; c++) acc[p][c] = 0ULL;

    for (int kc = 0; kc < 4; kc++) {
        for (int i = tid; i < 4096; i += 256) {
            int c = i >> 6, k = i & 63;
            ws[k * 68 + c] = __ldg(&w2[c * 256 + kc * 64 + k]);
        }
        for (int i = tid; i < 4096; i += 256) {
            int o = i >> 6, col = i & 63;
            hs[o * 68 + col] = g_h[b * 65536 + (kc * 64 + o) * 256 + n0b + col];
        }
        __syncthreads();
#pragma unroll 4
        for (int k = 0; k < 64; k++) {
            ulonglong2 wv = *(const ulonglong2*)(ws + k * 68 + ty * 4);  // ch pairs
            float4 hv = *(const float4*)(hs + k * 68 + tx * 4);
            u64 h0 = f2pack(hv.x, hv.x), h1 = f2pack(hv.y, hv.y);
            u64 h2 = f2pack(hv.z, hv.z), h3 = f2pack(hv.w, hv.w);
            acc[0][0] = ffma2(wv.x, h0, acc[0][0]);
            acc[0][1] = ffma2(wv.x, h1, acc[0][1]);
            acc[0][2] = ffma2(wv.x, h2, acc[0][2]);
            acc[0][3] = ffma2(wv.x, h3, acc[0][3]);
            acc[1][0] = ffma2(wv.y, h0, acc[1][0]);
            acc[1][1] = ffma2(wv.y, h1, acc[1][1]);
            acc[1][2] = ffma2(wv.y, h2, acc[1][2]);
            acc[1][3] = ffma2(wv.y, h3, acc[1][3]);
        }
        __syncthreads();
    }

    int n0 = n0b + tx * 4;
#pragma unroll
    for (int p = 0; p < 2; p++) {
        int ch0 = ty * 4 + 2 * p;
        float sc0, sh0, sc1s, sh1s;
        bn_coef(bn2, ch0, 64, sc0, sh0);
        bn_coef(bn2, ch0 + 1, 64, sc1s, sh1s);
        float4 f0 = *(const float4*)&g_f[b * 16384 + ch0 * 256 + n0];
        float4 f1 = *(const float4*)&g_f[b * 16384 + (ch0 + 1) * 256 + n0];
        float4 r0, r1;
        float a, bb;
        unpack2(acc[p][0], a, bb); r0.x = fmaxf(fmaf(a, sc0, sh0) + f0.x, 0.f); r1.x = fmaxf(fmaf(bb, sc1s, sh1s) + f1.x, 0.f);
        unpack2(acc[p][1], a, bb); r0.y = fmaxf(fmaf(a, sc0, sh0) + f0.y, 0.f); r1.y = fmaxf(fmaf(bb, sc1s, sh1s) + f1.y, 0.f);
        unpack2(acc[p][2], a, bb); r0.z = fmaxf(fmaf(a, sc0, sh0) + f0.z, 0.f); r1.z = fmaxf(fmaf(bb, sc1s, sh1s) + f1.z, 0.f);
        unpack2(acc[p][3], a, bb); r0.w = fmaxf(fmaf(a, sc0, sh0) + f0.w, 0.f); r1.w = fmaxf(fmaf(bb, sc1s, sh1s) + f1.w, 0.f);
        *(float4*)&out[b * 16384 + ch0 * 256 + n0]       = r0;
        *(float4*)&out[b * 16384 + (ch0 + 1) * 256 + n0] = r1;
    }
}

// ---------------- launch ----------------
extern "C" void kernel_launch(void* const* d_in, const int* in_sizes, int n_in,
                              void* d_out, int out_size) {
    int base = (in_sizes[2] == 512) ? 2 : 3;

    const float* x          = (const float*)d_in[0];
    const int*   stroke     = (const int*)d_in[1];
    const float* ga_q_w     = (const float*)d_in[base + 0];
    const float* ga_k_w     = (const float*)d_in[base + 1];
    const float* ga_v_w     = (const float*)d_in[base + 2];
    const float* ga_v_b     = (const float*)d_in[base + 3];
    const float* ga_bn_p    = (const float*)d_in[base + 4];
    const float* ga_lb_w    = (const float*)d_in[base + 5];
    const float* ga_lb_bn_p = (const float*)d_in[base + 6];
    const float* sa_q_w     = (const float*)d_in[base + 7];
    const float* sa_k_w     = (const float*)d_in[base + 8];
    const float* sa_v_w     = (const float*)d_in[base + 9];
    const float* sa_v_b     = (const float*)d_in[base + 10];
    const float* sa_bn_p    = (const float*)d_in[base + 11];
    const float* sa_lb_w    = (const float*)d_in[base + 12];
    const float* sa_lb_bn_p = (const float*)d_in[base + 13];
    const float* mlp_w1     = (const float*)d_in[base + 14];
    const float* mlp_bn1_p  = (const float*)d_in[base + 15];
    const float* mlp_w2     = (const float*)d_in[base + 16];
    const float* mlp_bn2_p  = (const float*)d_in[base + 17];

    cudaFuncSetAttribute(attn_kernel, cudaFuncAttributeMaxDynamicSharedMemorySize, ATTN_SMEM_BYTES);
    cudaFuncSetAttribute(mlp1_kernel, cudaFuncAttributeMaxDynamicSharedMemorySize, M1_SMEM_BYTES);
    cudaFuncSetAttribute(mlp2_kernel, cudaFuncAttributeMaxDynamicSharedMemorySize, M2_SMEM_BYTES);

    proj_kernel<<<dim3(64, 16), 128>>>(x, ga_q_w, ga_k_w, ga_v_w, ga_lb_w,
                                       sa_q_w, sa_k_w, sa_v_w, sa_lb_w);
    attn_kernel<<<dim3(64, 4), 256, ATTN_SMEM_BYTES>>>(stroke, ga_v_b, sa_v_b,
                                                       ga_bn_p, ga_lb_bn_p,
                                                       sa_bn_p, sa_lb_bn_p);
    mlp1_kernel<<<dim3(8, 64), 256, M1_SMEM_BYTES>>>(mlp_w1, mlp_bn1_p);
    mlp2_kernel<<<dim3(4, 64), 256, M2_SMEM_BYTES>>>(mlp_w2, mlp_bn2_p, (float*)d_out);
}

// round 6
// speedup vs baseline: 1.5966x; 1.0821x over previous
#include <cuda_runtime.h>
#include <math.h>

#define BATCH 64
#define CH    64
#define NPT   256

typedef unsigned long long u64;

// ---------------- global scratch ----------------
// g_proj rows per batch: 0-7 ga_q, 8-15 ga_k, 16-47 ga_v(raw), 48-55 sa_q,
// 56-63 sa_k, 64-95 sa_v(raw), 96-127 ga_lb, 128-159 sa_lb
__device__ float g_proj[BATCH * 160 * NPT];
__device__ float g_f[BATCH * CH * NPT];
__device__ float g_h[BATCH * 256 * NPT];   // MLP hidden, 16 MB (L2-resident)

// ---------------- f32x2 helpers ----------------
__device__ __forceinline__ u64 f2pack(float a, float b) {
    u64 r;
    asm("mov.b64 %0, {%1, %2};" : "=l"(r) : "r"(__float_as_uint(a)), "r"(__float_as_uint(b)));
    return r;
}
__device__ __forceinline__ u64 ffma2(u64 a, u64 b, u64 c) {
    u64 d;
    asm("fma.rn.f32x2 %0, %1, %2, %3;" : "=l"(d) : "l"(a), "l"(b), "l"(c));
    return d;
}
__device__ __forceinline__ u64 fadd2(u64 a, u64 b) {
    u64 d;
    asm("add.rn.f32x2 %0, %1, %2;" : "=l"(d) : "l"(a), "l"(b));
    return d;
}
__device__ __forceinline__ void unpack2(u64 v, float& lo, float& hi) {
    unsigned int l, h;
    asm("mov.b64 {%0, %1}, %2;" : "=r"(l), "=r"(h) : "l"(v));
    lo = __uint_as_float(l);
    hi = __uint_as_float(h);
}
__device__ __forceinline__ float hsum2(u64 v) {
    float lo, hi;
    unpack2(v, lo, hi);
    return lo + hi;
}
__device__ __forceinline__ void bn_coef(const float* __restrict__ p, int ch, int cn,
                                        float& sc, float& sh) {
    float ga = __ldg(p + ch);
    float be = __ldg(p + cn + ch);
    float mu = __ldg(p + 2 * cn + ch);
    float va = __ldg(p + 3 * cn + ch);
    sc = ga * rsqrtf(va + 1e-5f);
    sh = fmaf(-mu, sc, be);
}

// ---------------- kernel 1: projections ----------------
// grid (64, 16): y>>1 = out group (20 rows), y&1 = n half. block 128.
__global__ void proj_kernel(const float* __restrict__ x,
                            const float* __restrict__ ga_q_w, const float* __restrict__ ga_k_w,
                            const float* __restrict__ ga_v_w, const float* __restrict__ ga_lb_w,
                            const float* __restrict__ sa_q_w, const float* __restrict__ sa_k_w,
                            const float* __restrict__ sa_v_w, const float* __restrict__ sa_lb_w) {
    __shared__ float ws[20 * 64];
    int b = blockIdx.x, tid = threadIdx.x;
    int og = blockIdx.y >> 1, nh = blockIdx.y & 1;
    int n = nh * 128 + tid;

    for (int i = tid; i < 1280; i += 128) {
        int r = og * 20 + (i >> 6), c = i & 63;
        float v;
        if      (r < 8)   v = __ldg(&ga_q_w[r * 64 + c]);
        else if (r < 16)  v = __ldg(&ga_k_w[(r - 8) * 64 + c]);
        else if (r < 48)  v = __ldg(&ga_v_w[(r - 16) * 64 + c]);
        else if (r < 56)  v = __ldg(&sa_q_w[(r - 48) * 64 + c]);
        else if (r < 64)  v = __ldg(&sa_k_w[(r - 56) * 64 + c]);
        else if (r < 96)  v = __ldg(&sa_v_w[(r - 64) * 64 + c]);
        else if (r < 128) v = __ldg(&ga_lb_w[(r - 96) * 64 + c]);
        else              v = __ldg(&sa_lb_w[(r - 128) * 64 + c]);
        ws[i] = v;
    }
    __syncthreads();

    u64 xr2[32];
#pragma unroll
    for (int c = 0; c < 32; c++) {
        float a = __ldg(&x[b * 16384 + (2 * c) * 256 + n]);
        float bb = __ldg(&x[b * 16384 + (2 * c + 1) * 256 + n]);
        xr2[c] = f2pack(a, bb);
    }

    float* outp = g_proj + (b * 160 + og * 20) * 256 + n;
#pragma unroll 2
    for (int o = 0; o < 20; o++) {
        const ulonglong2* w2 = (const ulonglong2*)(ws + o * 64);
        u64 a0 = 0ULL, a1 = 0ULL;
#pragma unroll
        for (int i = 0; i < 16; i++) {
            ulonglong2 wv = w2[i];
            a0 = ffma2(wv.x, xr2[2 * i], a0);
            a1 = ffma2(wv.y, xr2[2 * i + 1], a1);
        }
        outp[o * 256] = hsum2(fadd2(a0, a1));
    }
}

// ---------------- kernel 2: attention ----------------
// grid (64, 4): y>>1 = branch, y&1 = row half. block 256 = 128 rows x 2 m-halves.
#define KS_OFF  0
#define VS_OFF  2048
#define MB_OFF  11264     // 4352 floats: SA bins (16x256) / V-merge (128x17 u64)
#define MX_OFF  15616
#define EB_OFF  15872
#define STK_OFF 16128
#define ATTN_SMEM_BYTES (16384 * 4)

__global__ void attn_kernel(const int* __restrict__ stroke_idx,
                            const float* __restrict__ ga_v_b, const float* __restrict__ sa_v_b,
                            const float* __restrict__ ga_bn_p, const float* __restrict__ ga_lb_bn_p,
                            const float* __restrict__ sa_bn_p, const float* __restrict__ sa_lb_bn_p) {
    extern __shared__ float sm[];
    float* Ks   = sm + KS_OFF;     // [m*8 + j]
    float* Vs   = sm + VS_OFF;     // [m*36 + o]
    float* MB   = sm + MB_OFF;     // bins [s*256+tid] then V-merge
    float* MX   = sm + MX_OFF;
    float* EB   = sm + EB_OFF;
    int*   stk  = (int*)(sm + STK_OFF);

    int b = blockIdx.x, tid = threadIdx.x;
    int branch = blockIdx.y >> 1, rh = blockIdx.y & 1;
    int row = tid & 127, mh = tid >> 7;
    int n = rh * 128 + row;
    int m0 = mh * 128;

    int qbase  = branch ? 48 : 0;
    int kbase  = qbase + 8;
    int vbase  = branch ? 64 : 16;
    int lbbase = branch ? 128 : 96;
    const float* vb = branch ? sa_v_b : ga_v_b;
    const float* gp = g_proj + b * 160 * 256;

    for (int i = tid; i < 2048; i += 256) {
        int r = i >> 8, m = i & 255;
        Ks[m * 8 + r] = gp[(kbase + r) * 256 + m];
    }
    for (int i = tid; i < 8192; i += 256) {
        int r = i >> 8, m = i & 255;
        Vs[m * 36 + r] = gp[(vbase + r) * 256 + m] + __ldg(vb + r);
    }
    if (branch)
        for (int i = tid; i < 256; i += 256) stk[i] = stroke_idx[b * 256 + i];
    __syncthreads();

    u64 q2[4];
#pragma unroll
    for (int j = 0; j < 4; j++)
        q2[j] = f2pack(gp[(qbase + 2 * j) * 256 + n], gp[(qbase + 2 * j + 1) * 256 + n]);

    const float INV_GA = 0.35355339059327373f;   // 1/sqrt(8)
    const float ESC    = 3.5355339059327378f;    // 10/sqrt(8)

    // ---- max over own m half, then partner merge ----
    float mxl = -1e30f;
#pragma unroll 4
    for (int m = m0; m < m0 + 128; m++) {
        const ulonglong2* k2 = (const ulonglong2*)(Ks + m * 8);
        ulonglong2 ka = k2[0], kb = k2[1];
        u64 d0 = ffma2(q2[0], ka.x, 0ULL);
        d0 = ffma2(q2[1], ka.y, d0);
        d0 = ffma2(q2[2], kb.x, d0);
        d0 = ffma2(q2[3], kb.y, d0);
        mxl = fmaxf(mxl, hsum2(d0));
    }
    MX[tid] = mxl;
    __syncthreads();
    float mx = fmaxf(MX[row], MX[row + 128]);

    u64 o2[16];
#pragma unroll
    for (int v = 0; v < 16; v++) o2[v] = 0ULL;
    u64* mb64 = (u64*)MB;

    if (branch == 0) {
        // ---- GA ----
        float sum = 0.f;
#pragma unroll 2
        for (int m = m0; m < m0 + 128; m++) {
            const ulonglong2* k2 = (const ulonglong2*)(Ks + m * 8);
            ulonglong2 ka = k2[0], kb = k2[1];
            u64 d0 = ffma2(q2[0], ka.x, 0ULL);
            d0 = ffma2(q2[1], ka.y, d0);
            d0 = ffma2(q2[2], kb.x, d0);
            d0 = ffma2(q2[3], kb.y, d0);
            float e = __expf((hsum2(d0) - mx) * INV_GA);
            sum += e;
            u64 ep = f2pack(e, e);
            const ulonglong2* v2p = (const ulonglong2*)(Vs + m * 36);
#pragma unroll
            for (int g = 0; g < 8; g++) {
                ulonglong2 vv = v2p[g];
                o2[2 * g]     = ffma2(ep, vv.x, o2[2 * g]);
                o2[2 * g + 1] = ffma2(ep, vv.y, o2[2 * g + 1]);
            }
        }
        EB[tid] = sum;
        __syncthreads();
        float sumt = EB[row] + EB[row + 128];
        if (mh == 1) {
#pragma unroll
            for (int j = 0; j < 16; j++) mb64[row * 17 + j] = o2[j];
        }
        __syncthreads();
        if (mh == 0) {
            float rcp = 1.f / sumt;
#pragma unroll
            for (int g = 0; g < 16; g++) {
                o2[g] = fadd2(o2[g], mb64[row * 17 + g]);
                float v0, v1;
                unpack2(o2[g], v0, v1);
                int c0 = 2 * g;
                float sc1, sh1, sc2, sh2;
                bn_coef(ga_bn_p, c0, 32, sc1, sh1);
                bn_coef(ga_lb_bn_p, c0, 32, sc2, sh2);
                float lb0 = gp[(lbbase + c0) * 256 + n];
                g_f[b * 16384 + c0 * 256 + n] = fmaf(v0 * rcp, sc1, sh1) + fmaf(lb0, sc2, sh2);
                bn_coef(ga_bn_p, c0 + 1, 32, sc1, sh1);
                bn_coef(ga_lb_bn_p, c0 + 1, 32, sc2, sh2);
                float lb1 = gp[(lbbase + c0 + 1) * 256 + n];
                g_f[b * 16384 + (c0 + 1) * 256 + n] = fmaf(v1 * rcp, sc1, sh1) + fmaf(lb1, sc2, sh2);
            }
        }
    } else {
        // ---- SA: collapsed 16-stroke masked softmax sum ----
        const float CC  = 1.00001000005f;
        const float CM1 = 1.00000500002e-05f;
#pragma unroll
        for (int s = 0; s < 16; s++) MB[s * 256 + tid] = 0.f;
        __syncthreads();
        float E = 0.f;
#pragma unroll 2
        for (int m = m0; m < m0 + 128; m++) {
            const ulonglong2* k2 = (const ulonglong2*)(Ks + m * 8);
            ulonglong2 ka = k2[0], kb = k2[1];
            u64 d0 = ffma2(q2[0], ka.x, 0ULL);
            d0 = ffma2(q2[1], ka.y, d0);
            d0 = ffma2(q2[2], kb.x, d0);
            d0 = ffma2(q2[3], kb.y, d0);
            float e = __expf((hsum2(d0) - mx) * ESC);
            E += e;
            MB[stk[m] * 256 + tid] += e;
        }
        EB[tid] = E;
        __syncthreads();
        if (mh == 0) {
            float Et = EB[row] + EB[row + 128];
            float zi[16];
            float Sinv = 0.f;
#pragma unroll
            for (int s = 0; s < 16; s++) {
                float bsum = MB[s * 256 + row] + MB[s * 256 + row + 128];
                float z = fmaf(-CM1, bsum, CC * Et);
                zi[s] = 1.f / z;
                Sinv += zi[s];
            }
#pragma unroll
            for (int s = 0; s < 16; s++)
                MB[s * 256 + row] = fmaf(-CM1, zi[s], CC * Sinv);   // coef_s
        }
        __syncthreads();
#pragma unroll 2
        for (int m = m0; m < m0 + 128; m++) {
            const ulonglong2* k2 = (const ulonglong2*)(Ks + m * 8);
            ulonglong2 ka = k2[0], kb = k2[1];
            u64 d0 = ffma2(q2[0], ka.x, 0ULL);
            d0 = ffma2(q2[1], ka.y, d0);
            d0 = ffma2(q2[2], kb.x, d0);
            d0 = ffma2(q2[3], kb.y, d0);
            float e = __expf((hsum2(d0) - mx) * ESC);
            float w = e * MB[stk[m] * 256 + row];
            u64 wp = f2pack(w, w);
            const ulonglong2* v2p = (const ulonglong2*)(Vs + m * 36);
#pragma unroll
            for (int g = 0; g < 8; g++) {
                ulonglong2 vv = v2p[g];
                o2[2 * g]     = ffma2(wp, vv.x, o2[2 * g]);
                o2[2 * g + 1] = ffma2(wp, vv.y, o2[2 * g + 1]);
            }
        }
        __syncthreads();   // bins done; reuse MB for V merge
        if (mh == 1) {
#pragma unroll
            for (int j = 0; j < 16; j++) mb64[row * 17 + j] = o2[j];
        }
        __syncthreads();
        if (mh == 0) {
#pragma unroll
            for (int g = 0; g < 16; g++) {
                o2[g] = fadd2(o2[g], mb64[row * 17 + g]);
                float v0, v1;
                unpack2(o2[g], v0, v1);
                int c0 = 2 * g;
                float sc1, sh1, sc2, sh2;
                bn_coef(sa_bn_p, c0, 32, sc1, sh1);
                bn_coef(sa_lb_bn_p, c0, 32, sc2, sh2);
                float lb0 = gp[(lbbase + c0) * 256 + n];
                g_f[b * 16384 + (32 + c0) * 256 + n] = fmaf(v0, sc1, sh1) + fmaf(lb0, sc2, sh2);
                bn_coef(sa_bn_p, c0 + 1, 32, sc1, sh1);
                bn_coef(sa_lb_bn_p, c0 + 1, 32, sc2, sh2);
                float lb1 = gp[(lbbase + c0 + 1) * 256 + n];
                g_f[b * 16384 + (32 + c0 + 1) * 256 + n] = fmaf(v1, sc1, sh1) + fmaf(lb1, sc2, sh2);
            }
        }
    }
}

// ---------------- kernel 3a: MLP stage 1 (h = relu(bn1(w1@f))) ----------------
// grid (8, 64): bx>>1 = ch chunk (64 of 256), bx&1 = col chunk (128). block 256.
#define M1_W_OFF 0
#define M1_F_OFF 4352                       // w1s = 64*68
#define M1_SMEM_BYTES ((4352 + 8448) * 4)   // + fs = 64*132

__global__ void mlp1_kernel(const float* __restrict__ w1, const float* __restrict__ bn1) {
    extern __shared__ float sm[];
    float* w1s = sm + M1_W_OFF;   // [k*68 + o]
    float* fs  = sm + M1_F_OFF;   // [k*132 + col]

    int b = blockIdx.y, tid = threadIdx.x;
    int cc = blockIdx.x >> 1, nc = blockIdx.x & 1;
    int tx = tid & 31, ty = tid >> 5;

    for (int i = tid; i < 4096; i += 256) {
        int o = i >> 6, k = i & 63;
        w1s[k * 68 + o] = __ldg(&w1[(cc * 64 + o) * 64 + k]);
    }
    for (int i = tid; i < 8192; i += 256) {
        int k = i >> 7, col = i & 127;
        fs[k * 132 + col] = g_f[b * 16384 + k * 256 + nc * 128 + col];
    }
    __syncthreads();

    // thread tile: 8 ch (4 pairs) x 4 cols
    u64 acc[4][4];
#pragma unroll
    for (int p = 0; p < 4; p++)
#pragma unroll
        for (int c = 0; c < 4; c++) acc[p][c] = 0ULL;

#pragma unroll 4
    for (int k = 0; k < 64; k++) {
        const ulonglong2* wv2 = (const ulonglong2*)(w1s + k * 68 + ty * 8);
        ulonglong2 wa = wv2[0], wb = wv2[1];            // ch pairs (0,1),(2,3)
        float4 hv = *(const float4*)(fs + k * 132 + tx * 4);
        u64 h0 = f2pack(hv.x, hv.x), h1 = f2pack(hv.y, hv.y);
        u64 h2 = f2pack(hv.z, hv.z), h3 = f2pack(hv.w, hv.w);
        acc[0][0] = ffma2(wa.x, h0, acc[0][0]);
        acc[0][1] = ffma2(wa.x, h1, acc[0][1]);
        acc[0][2] = ffma2(wa.x, h2, acc[0][2]);
        acc[0][3] = ffma2(wa.x, h3, acc[0][3]);
        acc[1][0] = ffma2(wa.y, h0, acc[1][0]);
        acc[1][1] = ffma2(wa.y, h1, acc[1][1]);
        acc[1][2] = ffma2(wa.y, h2, acc[1][2]);
        acc[1][3] = ffma2(wa.y, h3, acc[1][3]);
        acc[2][0] = ffma2(wb.x, h0, acc[2][0]);
        acc[2][1] = ffma2(wb.x, h1, acc[2][1]);
        acc[2][2] = ffma2(wb.x, h2, acc[2][2]);
        acc[2][3] = ffma2(wb.x, h3, acc[2][3]);
        acc[3][0] = ffma2(wb.y, h0, acc[3][0]);
        acc[3][1] = ffma2(wb.y, h1, acc[3][1]);
        acc[3][2] = ffma2(wb.y, h2, acc[3][2]);
        acc[3][3] = ffma2(wb.y, h3, acc[3][3]);
    }

    int n0 = nc * 128 + tx * 4;
#pragma unroll
    for (int p = 0; p < 4; p++) {
        int ch0 = cc * 64 + ty * 8 + 2 * p;
        float sc0, sh0, sc1s, sh1s;
        bn_coef(bn1, ch0, 256, sc0, sh0);
        bn_coef(bn1, ch0 + 1, 256, sc1s, sh1s);
        float4 r0, r1;
        float a, bb;
        unpack2(acc[p][0], a, bb); r0.x = fmaxf(fmaf(a, sc0, sh0), 0.f); r1.x = fmaxf(fmaf(bb, sc1s, sh1s), 0.f);
        unpack2(acc[p][1], a, bb); r0.y = fmaxf(fmaf(a, sc0, sh0), 0.f); r1.y = fmaxf(fmaf(bb, sc1s, sh1s), 0.f);
        unpack2(acc[p][2], a, bb); r0.z = fmaxf(fmaf(a, sc0, sh0), 0.f); r1.z = fmaxf(fmaf(bb, sc1s, sh1s), 0.f);
        unpack2(acc[p][3], a, bb); r0.w = fmaxf(fmaf(a, sc0, sh0), 0.f); r1.w = fmaxf(fmaf(bb, sc1s, sh1s), 0.f);
        *(float4*)&g_h[b * 65536 + ch0 * 256 + n0]       = r0;
        *(float4*)&g_h[b * 65536 + (ch0 + 1) * 256 + n0] = r1;
    }
}

// ---------------- kernel 3b: MLP stage 2, single pass ----------------
// grid (4, 64): bx = col chunk (64). block 256. h tile resident in smem,
// w2 streamed via warp-broadcast LDG.128 (no inner barriers).
#define M2_SMEM_BYTES (256 * 68 * 4)

__global__ void mlp2_kernel(const float* __restrict__ w2, const float* __restrict__ bn2,
                            float* __restrict__ out) {
    extern __shared__ float sm[];
    float* hs = sm;   // [k*68 + col], k=0..255, col=0..63

    int b = blockIdx.y, tid = threadIdx.x;
    int n0b = blockIdx.x * 64;

    // load full h tile: 256 k x 64 cols, vectorized
    for (int i = tid; i < 4096; i += 256) {
        int k = i >> 4, col0 = (i & 15) * 4;
        float4 v = *(const float4*)&g_h[b * 65536 + k * 256 + n0b + col0];
        *(float4*)(hs + k * 68 + col0) = v;
    }
    __syncthreads();

    int tx = tid & 15, ty = tid >> 4;
    int c0 = ty * 4, col0 = tx * 4;

    u64 acc[4][2];
#pragma unroll
    for (int j = 0; j < 4; j++) { acc[j][0] = 0ULL; acc[j][1] = 0ULL; }

#pragma unroll 2
    for (int k4 = 0; k4 < 256; k4 += 4) {
        float4 w[4];
#pragma unroll
        for (int j = 0; j < 4; j++)
            w[j] = __ldg((const float4*)&w2[(c0 + j) * 256 + k4]);
#pragma unroll
        for (int kk = 0; kk < 4; kk++) {
            ulonglong2 hv = *(const ulonglong2*)(hs + (k4 + kk) * 68 + col0);
#pragma unroll
            for (int j = 0; j < 4; j++) {
                float wv = (kk == 0) ? w[j].x : (kk == 1) ? w[j].y : (kk == 2) ? w[j].z : w[j].w;
                u64 wp = f2pack(wv, wv);
                acc[j][0] = ffma2(wp, hv.x, acc[j][0]);
                acc[j][1] = ffma2(wp, hv.y, acc[j][1]);
            }
        }
    }

    int n0 = n0b + col0;
#pragma unroll
    for (int j = 0; j < 4; j++) {
        int c = c0 + j;
        float sc, sh;
        bn_coef(bn2, c, 64, sc, sh);
        float4 f0 = *(const float4*)&g_f[b * 16384 + c * 256 + n0];
        float v0, v1, v2, v3;
        unpack2(acc[j][0], v0, v1);
        unpack2(acc[j][1], v2, v3);
        float4 r;
        r.x = fmaxf(fmaf(v0, sc, sh) + f0.x, 0.f);
        r.y = fmaxf(fmaf(v1, sc, sh) + f0.y, 0.f);
        r.z = fmaxf(fmaf(v2, sc, sh) + f0.z, 0.f);
        r.w = fmaxf(fmaf(v3, sc, sh) + f0.w, 0.f);
        *(float4*)&out[b * 16384 + c * 256 + n0] = r;
    }
}

// ---------------- launch ----------------
extern "C" void kernel_launch(void* const* d_in, const int* in_sizes, int n_in,
                              void* d_out, int out_size) {
    int base = (in_sizes[2] == 512) ? 2 : 3;

    const float* x          = (const float*)d_in[0];
    const int*   stroke     = (const int*)d_in[1];
    const float* ga_q_w     = (const float*)d_in[base + 0];
    const float* ga_k_w     = (const float*)d_in[base + 1];
    const float* ga_v_w     = (const float*)d_in[base + 2];
    const float* ga_v_b     = (const float*)d_in[base + 3];
    const float* ga_bn_p    = (const float*)d_in[base + 4];
    const float* ga_lb_w    = (const float*)d_in[base + 5];
    const float* ga_lb_bn_p = (const float*)d_in[base + 6];
    const float* sa_q_w     = (const float*)d_in[base + 7];
    const float* sa_k_w     = (const float*)d_in[base + 8];
    const float* sa_v_w     = (const float*)d_in[base + 9];
    const float* sa_v_b     = (const float*)d_in[base + 10];
    const float* sa_bn_p    = (const float*)d_in[base + 11];
    const float* sa_lb_w    = (const float*)d_in[base + 12];
    const float* sa_lb_bn_p = (const float*)d_in[base + 13];
    const float* mlp_w1     = (const float*)d_in[base + 14];
    const float* mlp_bn1_p  = (const float*)d_in[base + 15];
    const float* mlp_w2     = (const float*)d_in[base + 16];
    const float* mlp_bn2_p  = (const float*)d_in[base + 17];

    cudaFuncSetAttribute(attn_kernel, cudaFuncAttributeMaxDynamicSharedMemorySize, ATTN_SMEM_BYTES);
    cudaFuncSetAttribute(mlp1_kernel, cudaFuncAttributeMaxDynamicSharedMemorySize, M1_SMEM_BYTES);
    cudaFuncSetAttribute(mlp2_kernel, cudaFuncAttributeMaxDynamicSharedMemorySize, M2_SMEM_BYTES);

    proj_kernel<<<dim3(64, 16), 128>>>(x, ga_q_w, ga_k_w, ga_v_w, ga_lb_w,
                                       sa_q_w, sa_k_w, sa_v_w, sa_lb_w);
    attn_kernel<<<dim3(64, 4), 256, ATTN_SMEM_BYTES>>>(stroke, ga_v_b, sa_v_b,
                                                       ga_bn_p, ga_lb_bn_p,
                                                       sa_bn_p, sa_lb_bn_p);
    mlp1_kernel<<<dim3(8, 64), 256, M1_SMEM_BYTES>>>(mlp_w1, mlp_bn1_p);
    mlp2_kernel<<<dim3(4, 64), 256, M2_SMEM_BYTES>>>(mlp_w2, mlp_bn2_p, (float*)d_out);
}